// round 9
// baseline (speedup 1.0000x reference)
#include <cuda_runtime.h>
#include <cuda_bf16.h>
#include <cuda_fp16.h>
#include <stdint.h>
#include <math.h>

#define N_NODES 50000
#define N_EDGES 600000
#define N_GRAPHS 512
#define GRID 148
#define NTH 256
#define MT_PAD 3128          // >= ceil(50000/16), padded to 391*8
#define NODES_PER_CTA 338    // ceil(50000/148)

// ---------------- device globals ---------------------------------------------
__device__ __half   g_yh[N_NODES * 128];
__device__ float    g_z[N_NODES * 128];
__device__ float    g_x2[N_NODES * 128];
__device__ uint32_t g_ah[MT_PAD * 8 * 128];
__device__ uint32_t g_al[MT_PAD * 8 * 128];
__device__ uint32_t g_wh[5 * 8192];
__device__ uint32_t g_wl[5 * 8192];
__device__ int      g_deg[N_NODES];
__device__ int      g_ptr[N_NODES + 1];
__device__ int      g_ptr2[N_NODES];
__device__ int      g_csr[N_EDGES];
__device__ int      g_gstart[N_GRAPHS + 1];
__device__ int      g_part[GRID];
__device__ unsigned int g_bar;   // monotonic ticket barrier (never reset)

// ---------------- grid-wide barrier (release/acquire) ------------------------
__device__ __forceinline__ void grid_sync() {
    __threadfence();     // RELEASE: publish this thread's stores
    __syncthreads();     // all threads of the block have fenced
    if (threadIdx.x == 0) {
        unsigned int ticket = atomicAdd(&g_bar, 1u);   // signal AFTER all fences
        unsigned int target = (ticket / GRID + 1u) * GRID;
        unsigned int cur;
        do {
            asm volatile("ld.acquire.gpu.global.u32 %0, [%1];" : "=r"(cur) : "l"(&g_bar));
        } while (cur < target);
    }
    __syncthreads();
    __threadfence();     // ACQUIRE: order subsequent loads
}

// ---------------- helpers ----------------------------------------------------
__device__ __forceinline__ uint32_t pack_split(float x, float y, uint32_t& lo) {
    __nv_bfloat16 hx = __float2bfloat16(x);
    __nv_bfloat16 hy = __float2bfloat16(y);
    float rx = x - __bfloat162float(hx);
    float ry = y - __bfloat162float(hy);
    __nv_bfloat16 lx = __float2bfloat16(rx);
    __nv_bfloat16 ly = __float2bfloat16(ry);
    uint16_t bhx = *reinterpret_cast<uint16_t*>(&hx);
    uint16_t bhy = *reinterpret_cast<uint16_t*>(&hy);
    uint16_t blx = *reinterpret_cast<uint16_t*>(&lx);
    uint16_t bly = *reinterpret_cast<uint16_t*>(&ly);
    lo = ((uint32_t)bly << 16) | blx;
    return ((uint32_t)bhy << 16) | bhx;
}

__device__ __forceinline__ uint32_t smem_u32(const void* p) {
    uint32_t a;
    asm("{ .reg .u64 t; cvta.to.shared.u64 t, %1; cvt.u32.u64 %0, t; }" : "=r"(a) : "l"(p));
    return a;
}

__device__ __forceinline__ void cp16(uint32_t dst, const void* src) {
    asm volatile("cp.async.cg.shared.global [%0], [%1], 16;" :: "r"(dst), "l"(src) : "memory");
}

#define MMA_BF16(c, a, b)                                                         \
    asm volatile(                                                                 \
        "mma.sync.aligned.m16n8k16.row.col.f32.bf16.bf16.f32 "                    \
        "{%0,%1,%2,%3},{%4,%5,%6,%7},{%8,%9},{%0,%1,%2,%3};"                      \
        : "+f"(c[0]), "+f"(c[1]), "+f"(c[2]), "+f"(c[3])                          \
        : "r"(a[0]), "r"(a[1]), "r"(a[2]), "r"(a[3]), "r"(b[0]), "r"(b[1]))

// ---------------- GEMM phase: persistent tiles --------------------------------
static __device__ void gemm_phase(char* smem, int nmat,
                                  const uint32_t* BhA, const uint32_t* BlA,
                                  const uint32_t* BhB, const uint32_t* BlB,
                                  bool layer2) {
    constexpr int NT = 16;
    constexpr int STAGE = 16384 + 16384;
    uint32_t sb = smem_u32(smem);
    int tid = threadIdx.x, lane = tid & 31, warp = tid >> 5;
    int wm = warp & 1, wn = warp >> 1;
    int gid = lane >> 2, tig = lane & 3;

    for (int t = blockIdx.x; t < 391 * nmat; t += GRID) {
        int mt = t % 391;
        int mat = t / 391;
        const uint32_t* Bh = mat ? BhB : BhA;
        const uint32_t* Bl = mat ? BlB : BlA;
        int bRow = mt * 128;

        float acc[4][4][4];
#pragma unroll
        for (int a = 0; a < 4; a++)
#pragma unroll
            for (int b = 0; b < 4; b++)
#pragma unroll
                for (int c = 0; c < 4; c++) acc[a][b][c] = 0.f;

        __syncthreads();  // protect smem reuse across tiles

        auto load_stage = [&](int kc, int buf) {
#pragma unroll
            for (int i = 0; i < 4; i++) {                 // A: 16KB
                int c = tid + i * 256;
                int tt = c >> 5, o = (c & 31) * 16;
                int pl = tt >> 4, kt = (tt >> 3) & 1, mtile = tt & 7;
                const uint32_t* src = (pl ? g_al : g_ah) +
                    ((mt * 8 + mtile) * 8 + kc * 2 + kt) * 128;
                cp16(sb + buf * STAGE + tt * 512 + o, (const char*)src + o);
            }
#pragma unroll
            for (int i = 0; i < 4; i++) {                 // B: 16KB
                int c = tid + i * 256;
                int tt = c >> 4, o = (c & 15) * 16;
                int pl = tt / 32;
                int kt = (tt / 16) & 1;
                int nt = tt % 16;
                const uint32_t* src = (pl ? Bl : Bh) + ((kc * 2 + kt) * NT + nt) * 64;
                cp16(sb + buf * STAGE + 16384 + tt * 256 + o, (const char*)src + o);
            }
            asm volatile("cp.async.commit_group;" ::: "memory");
        };

        auto compute = [&](int buf) {
#pragma unroll
            for (int kt = 0; kt < 2; kt++) {
                uint32_t a[2][4][4];
#pragma unroll
                for (int pl = 0; pl < 2; pl++)
#pragma unroll
                    for (int mtile = 0; mtile < 4; mtile++) {
                        uint32_t ad = sb + buf * STAGE +
                            (((pl * 2 + kt) * 8) + (wm * 4 + mtile)) * 512 + lane * 16;
                        asm volatile("ld.shared.v4.b32 {%0,%1,%2,%3},[%4];"
                            : "=r"(a[pl][mtile][0]), "=r"(a[pl][mtile][1]),
                              "=r"(a[pl][mtile][2]), "=r"(a[pl][mtile][3]) : "r"(ad));
                    }
                uint32_t b[2][4][2];
#pragma unroll
                for (int pl = 0; pl < 2; pl++)
#pragma unroll
                    for (int nt = 0; nt < 4; nt++) {
                        uint32_t ad = sb + buf * STAGE + 16384 +
                            ((pl * 2 + kt) * NT + wn * 4 + nt) * 256 + lane * 8;
                        asm volatile("ld.shared.v2.b32 {%0,%1},[%2];"
                            : "=r"(b[pl][nt][0]), "=r"(b[pl][nt][1]) : "r"(ad));
                    }
#pragma unroll
                for (int mtile = 0; mtile < 4; mtile++)
#pragma unroll
                    for (int nt = 0; nt < 4; nt++) {
                        MMA_BF16(acc[mtile][nt], a[0][mtile], b[0][nt]);
                        MMA_BF16(acc[mtile][nt], a[0][mtile], b[1][nt]);
                        MMA_BF16(acc[mtile][nt], a[1][mtile], b[0][nt]);
                    }
            }
        };

        load_stage(0, 0);
        for (int kc = 0; kc < 4; kc++) {
            if (kc < 3) {
                load_stage(kc + 1, (kc + 1) & 1);
                asm volatile("cp.async.wait_group 1;" ::: "memory");
            } else {
                asm volatile("cp.async.wait_group 0;" ::: "memory");
            }
            __syncthreads();
            compute(kc & 1);
            __syncthreads();
        }

#pragma unroll
        for (int mtile = 0; mtile < 4; mtile++) {
            int row = bRow + wm * 64 + mtile * 16 + gid;
#pragma unroll
            for (int nt = 0; nt < 4; nt++) {
                int col = wn * 32 + nt * 8 + tig * 2;
                bool f16dst = layer2 || (mat == 0);
                if (f16dst) {
                    if (row < N_NODES)
                        *reinterpret_cast<__half2*>(&g_yh[row * 128 + col]) =
                            __floats2half2_rn(acc[mtile][nt][0], acc[mtile][nt][1]);
                    if (row + 8 < N_NODES)
                        *reinterpret_cast<__half2*>(&g_yh[(row + 8) * 128 + col]) =
                            __floats2half2_rn(acc[mtile][nt][2], acc[mtile][nt][3]);
                } else {
                    if (row < N_NODES)
                        *reinterpret_cast<float2*>(&g_z[row * 128 + col]) =
                            make_float2(acc[mtile][nt][0], acc[mtile][nt][1]);
                    if (row + 8 < N_NODES)
                        *reinterpret_cast<float2*>(&g_z[(row + 8) * 128 + col]) =
                            make_float2(acc[mtile][nt][2], acc[mtile][nt][3]);
                }
            }
        }
    }
}

// ---------------- agg phase (128ch) + fragment pack --------------------------
static __device__ void agg128_phase(const float* bl, float* out_pre, float* out_x2) {
    int gw = blockIdx.x * 8 + (threadIdx.x >> 5);
    int lane = threadIdx.x & 31;
    for (int node = gw; node < N_NODES; node += GRID * 8) {
        int lo = g_ptr[node], hi = g_ptr[node + 1];
        float4 acc = make_float4(0.f, 0.f, 0.f, 0.f);
#pragma unroll 8
        for (int e = lo; e < hi; e++) {
            int s = g_csr[e];
            uint2 raw = __ldcg((const uint2*)(g_yh + s * 128 + lane * 4));
            __half2 p0 = *reinterpret_cast<__half2*>(&raw.x);
            __half2 p1 = *reinterpret_cast<__half2*>(&raw.y);
            float2 f0 = __half22float2(p0);
            float2 f1 = __half22float2(p1);
            acc.x += f0.x; acc.y += f0.y; acc.z += f1.x; acc.w += f1.y;
        }
        float inv = 1.f / (float)max(hi - lo, 1);
        float4 b = *reinterpret_cast<const float4*>(&bl[lane * 4]);
        float4 zi = __ldcg((const float4*)(g_z + node * 128 + lane * 4));
        float4 h;
        h.x = acc.x * inv + b.x + zi.x;
        h.y = acc.y * inv + b.y + zi.y;
        h.z = acc.z * inv + b.z + zi.z;
        h.w = acc.w * inv + b.w + zi.w;
        if (out_pre) *reinterpret_cast<float4*>(&out_pre[node * 128 + lane * 4]) = h;
        float4 r = make_float4(fmaxf(h.x, 0.f), fmaxf(h.y, 0.f),
                               fmaxf(h.z, 0.f), fmaxf(h.w, 0.f));
        if (out_x2) *reinterpret_cast<float4*>(&out_x2[node * 128 + lane * 4]) = r;

        int mt = node >> 4, gid = node & 7, rowhalf = (node >> 3) & 1;
        int kt = lane >> 2;
        float v01[2] = {r.x, r.z};
        float v11[2] = {r.y, r.w};
#pragma unroll
        for (int p = 0; p < 2; p++) {
            int c = lane * 4 + 2 * p;
            int ct = c & 15;
            int tig = (ct & 7) >> 1;
            int colhalf = ct >> 3;
            int reg = rowhalf + 2 * colhalf;
            int idx = ((mt * 8 + kt) * 32 + gid * 4 + tig) * 4 + reg;
            uint32_t lo32;
            uint32_t hi32 = pack_split(v01[p], v11[p], lo32);
            g_ah[idx] = hi32;
            g_al[idx] = lo32;
        }
    }
}

// ---------------- the mega kernel --------------------------------------------
__global__ void __launch_bounds__(NTH) mega_kernel(
    const float* __restrict__ x, const int* __restrict__ src,
    const int* __restrict__ dst, const int* __restrict__ cluster,
    const float* __restrict__ Wl0, const float* __restrict__ bl0, const float* __restrict__ Wr0,
    const float* __restrict__ Wl1, const float* __restrict__ bl1, const float* __restrict__ Wr1,
    const float* __restrict__ Wl2, const float* __restrict__ bl2, const float* __restrict__ Wr2,
    float* __restrict__ out_lsm, float* __restrict__ out_pre, float* __restrict__ out_g) {
    extern __shared__ char smem[];
    __shared__ int sred[256];
    int tid = threadIdx.x;
    int gtid = blockIdx.x * NTH + tid;
    int lane = tid & 31;
    int gw = blockIdx.x * 8 + (tid >> 5);
    const int GSTRIDE = GRID * NTH;       // 37888
    const int WSTRIDE = GRID * 8;         // 1184

    // ===== P0: zero deg, gstart, pack weights, pack A =====
    for (int i = gtid; i < N_NODES; i += GSTRIDE) g_deg[i] = 0;
    if (gtid <= N_GRAPHS) {
        if (gtid == N_GRAPHS) g_gstart[gtid] = N_NODES;
        else {
            int lo = 0, hi = N_NODES;
            while (lo < hi) {
                int mid = (lo + hi) >> 1;
                if (cluster[mid] < gtid) lo = mid + 1; else hi = mid;
            }
            g_gstart[gtid] = lo;
        }
    }
    // pack weights: 640 warp-items
    for (int it = gw; it < 640; it += WSTRIDE) {
        const float* W;
        int BNs, dst_mat, nt_off, tile;
        if (it < 512) {
            int m = it >> 7;
            tile = it & 127;
            BNs = 128; dst_mat = m; nt_off = 0;
            W = (m == 0) ? Wl0 : (m == 1) ? Wr0 : (m == 2) ? Wl1 : Wr1;
        } else {
            int m = (it - 512) >> 6;
            tile = (it - 512) & 63;
            BNs = 64; dst_mat = 4; nt_off = m ? 8 : 0;
            W = m ? Wr2 : Wl2;
        }
        int NTs = BNs / 8;
        int kt = tile / NTs, nt = tile % NTs;
        int gidl = lane >> 2, tig = lane & 3;
        int col = nt * 8 + gidl;
        uint32_t h[2], l[2];
#pragma unroll
        for (int r = 0; r < 2; r++) {
            int k = kt * 16 + tig * 2 + r * 8;
            float v0 = W[k * BNs + col];
            float v1 = W[(k + 1) * BNs + col];
            h[r] = pack_split(v0, v1, l[r]);
        }
        int didx = dst_mat * 8192 + (kt * 16 + nt + nt_off) * 64 + lane * 2;
        *reinterpret_cast<uint2*>(&g_wh[didx]) = make_uint2(h[0], h[1]);
        *reinterpret_cast<uint2*>(&g_wl[didx]) = make_uint2(l[0], l[1]);
    }
    // pack A (x input): MT_PAD*8 warp-items
    for (int it = gw; it < MT_PAD * 8; it += WSTRIDE) {
        int mt = it >> 3, kt = it & 7;
        int gidl = lane >> 2, tig = lane & 3;
        uint32_t h[4], l[4];
#pragma unroll
        for (int r = 0; r < 4; r++) {
            int row = mt * 16 + gidl + (r & 1) * 8;
            int col = kt * 16 + tig * 2 + (r >> 1) * 8;
            float2 v = make_float2(0.f, 0.f);
            if (row < N_NODES) v = *reinterpret_cast<const float2*>(&x[row * 128 + col]);
            h[r] = pack_split(v.x, v.y, l[r]);
        }
        *reinterpret_cast<uint4*>(&g_ah[(it * 32 + lane) * 4]) = make_uint4(h[0], h[1], h[2], h[3]);
        *reinterpret_cast<uint4*>(&g_al[(it * 32 + lane) * 4]) = make_uint4(l[0], l[1], l[2], l[3]);
    }
    grid_sync();

    // ===== P1: histogram =====
    for (int e = gtid; e < N_EDGES; e += GSTRIDE) atomicAdd(&g_deg[dst[e]], 1);
    grid_sync();

    // ===== P2a: per-CTA chunk sums =====
    int cbase = blockIdx.x * NODES_PER_CTA;
    int ccnt = min(NODES_PER_CTA, N_NODES - cbase);
    if (ccnt < 0) ccnt = 0;
    {
        int s = 0;
        for (int j = tid; j < ccnt; j += NTH) s += __ldcg(&g_deg[cbase + j]);
        sred[tid] = s;
        __syncthreads();
        for (int off = 128; off > 0; off >>= 1) {
            if (tid < off) sred[tid] += sred[tid + off];
            __syncthreads();
        }
        if (tid == 0) g_part[blockIdx.x] = sred[0];
    }
    grid_sync();

    // ===== P2b: offsets + block scan -> ptr, ptr2 =====
    {
        if (tid == 0) {
            int o = 0;
            for (int i = 0; i < (int)blockIdx.x; i++) o += __ldcg(&g_part[i]);
            sred[0] = o;
        }
        __syncthreads();
        int offset = sred[0];
        __syncthreads();
        int i0 = tid * 2, i1 = tid * 2 + 1;
        int d0 = (i0 < ccnt) ? __ldcg(&g_deg[cbase + i0]) : 0;
        int d1 = (i1 < ccnt) ? __ldcg(&g_deg[cbase + i1]) : 0;
        sred[tid] = d0 + d1;
        __syncthreads();
        for (int off = 1; off < 256; off <<= 1) {
            int v = (tid >= off) ? sred[tid - off] : 0;
            __syncthreads();
            sred[tid] += v;
            __syncthreads();
        }
        int excl = (tid == 0) ? 0 : sred[tid - 1];
        int p0 = offset + excl;
        if (i0 < ccnt) { g_ptr[cbase + i0] = p0; g_ptr2[cbase + i0] = p0; }
        if (i1 < ccnt) { g_ptr[cbase + i1] = p0 + d0; g_ptr2[cbase + i1] = p0 + d0; }
        if (blockIdx.x == 0 && tid == 0) g_ptr[N_NODES] = N_EDGES;
    }
    grid_sync();

    // ===== P3: fill CSR =====
    for (int e = gtid; e < N_EDGES; e += GSTRIDE) {
        int d = dst[e];
        int pos = atomicAdd(&g_ptr2[d], 1);
        g_csr[pos] = src[e];
    }
    grid_sync();

    // ===== P4: GEMM layer 0 =====
    gemm_phase(smem, 2, g_wh + 0 * 8192, g_wl + 0 * 8192,
               g_wh + 1 * 8192, g_wl + 1 * 8192, false);
    grid_sync();

    // ===== P5: agg 0 (+repack) =====
    agg128_phase(bl0, nullptr, nullptr);
    grid_sync();

    // ===== P6: GEMM layer 1 =====
    gemm_phase(smem, 2, g_wh + 2 * 8192, g_wl + 2 * 8192,
               g_wh + 3 * 8192, g_wl + 3 * 8192, false);
    grid_sync();

    // ===== P7: agg 1 (+out_pre, x2, repack) =====
    agg128_phase(bl1, out_pre, g_x2);
    grid_sync();

    // ===== P8: GEMM layer 2 (fused [Wl2|Wr2]) + pooling =====
    gemm_phase(smem, 1, g_wh + 4 * 8192, g_wl + 4 * 8192,
               g_wh + 4 * 8192, g_wl + 4 * 8192, true);
    for (int g = gw; g < N_GRAPHS; g += WSTRIDE) {
        int lo = __ldcg(&g_gstart[g]), hi = __ldcg(&g_gstart[g + 1]);
        float4 acc = make_float4(0.f, 0.f, 0.f, 0.f);
        for (int i = lo; i < hi; i++) {
            float4 v = __ldcg((const float4*)(g_x2 + i * 128 + lane * 4));
            acc.x += v.x; acc.y += v.y; acc.z += v.z; acc.w += v.w;
        }
        float inv = 1.f / (float)max(hi - lo, 1);
        acc.x *= inv; acc.y *= inv; acc.z *= inv; acc.w *= inv;
        *reinterpret_cast<float4*>(&out_g[g * 128 + lane * 4]) = acc;
    }
    grid_sync();

    // ===== P9: final agg (64ch) + log_softmax =====
    for (int node = gw; node < N_NODES; node += WSTRIDE) {
        int lo = g_ptr[node], hi = g_ptr[node + 1];
        float2 acc = make_float2(0.f, 0.f);
#pragma unroll 8
        for (int e = lo; e < hi; e++) {
            int s = g_csr[e];
            unsigned int raw = __ldcg((const unsigned int*)(g_yh + s * 128 + lane * 2));
            float2 f = __half22float2(*reinterpret_cast<__half2*>(&raw));
            acc.x += f.x; acc.y += f.y;
        }
        float inv = 1.f / (float)max(hi - lo, 1);
        float2 b = *reinterpret_cast<const float2*>(&bl2[lane * 2]);
        unsigned int zraw = __ldcg((const unsigned int*)(g_yh + node * 128 + 64 + lane * 2));
        float2 zi = __half22float2(*reinterpret_cast<__half2*>(&zraw));
        float2 h;
        h.x = acc.x * inv + b.x + zi.x;
        h.y = acc.y * inv + b.y + zi.y;

        float m = fmaxf(h.x, h.y);
#pragma unroll
        for (int off = 16; off > 0; off >>= 1)
            m = fmaxf(m, __shfl_xor_sync(0xFFFFFFFFu, m, off));
        float s = expf(h.x - m) + expf(h.y - m);
#pragma unroll
        for (int off = 16; off > 0; off >>= 1)
            s += __shfl_xor_sync(0xFFFFFFFFu, s, off);
        float ls = logf(s);
        *reinterpret_cast<float2*>(&out_lsm[node * 64 + lane * 2]) =
            make_float2(h.x - m - ls, h.y - m - ls);
    }
}

// ---------------- launch -----------------------------------------------------
extern "C" void kernel_launch(void* const* d_in, const int* in_sizes, int n_in,
                              void* d_out, int out_size) {
    const float* x       = (const float*)d_in[0];
    const int*   ei      = (const int*)d_in[1];
    const int*   cluster = (const int*)d_in[2];
    const float* Wl0 = (const float*)d_in[3];
    const float* bl0 = (const float*)d_in[4];
    const float* Wr0 = (const float*)d_in[5];
    const float* Wl1 = (const float*)d_in[6];
    const float* bl1 = (const float*)d_in[7];
    const float* Wr1 = (const float*)d_in[8];
    const float* Wl2 = (const float*)d_in[9];
    const float* bl2 = (const float*)d_in[10];
    const float* Wr2 = (const float*)d_in[11];

    const int* src = ei;
    const int* dst = ei + N_EDGES;

    float* out = (float*)d_out;
    float* out_lsm = out;
    float* out_pre = out + N_NODES * 64;
    float* out_g   = out + N_NODES * 64 + N_NODES * 128;

    const int SMEM = 2 * (16384 + 16384);  // 64 KB
    cudaFuncSetAttribute(mega_kernel, cudaFuncAttributeMaxDynamicSharedMemorySize, SMEM);

    mega_kernel<<<GRID, NTH, SMEM>>>(x, src, dst, cluster,
                                     Wl0, bl0, Wr0, Wl1, bl1, Wr1, Wl2, bl2, Wr2,
                                     out_lsm, out_pre, out_g);
}

// round 10
// speedup vs baseline: 2.1421x; 2.1421x over previous
#include <cuda_runtime.h>
#include <cuda_bf16.h>
#include <cuda_fp16.h>
#include <math.h>
#include <stdint.h>

#define N_NODES 50000
#define N_EDGES 600000
#define C_HID 128
#define C_OUT 64
#define N_GRAPHS 512
#define MT_PAD 3128     // 391*8 m-tiles of 16 rows
#define NCHUNK 196      // ceil(50000/256)
#define AGG_BLOCKS 6250 // 50000/8 warps

// ---------------- scratch (__device__ globals) -------------------------------
__device__ __half   g_yh[N_NODES * 128];
__device__ float    g_z[N_NODES * 128];
__device__ float    g_x2[N_NODES * 128];
__device__ uint32_t g_ah[MT_PAD * 8 * 128];
__device__ uint32_t g_al[MT_PAD * 8 * 128];
__device__ uint32_t g_wh[5 * 8192];
__device__ uint32_t g_wl[5 * 8192];
__device__ int      g_deg[N_NODES];      // zeroed at end of each run
__device__ int      g_fill[N_NODES];     // zeroed at end of each run
__device__ int      g_ptrL[N_NODES];     // local (per-256-chunk) exclusive scan
__device__ int      g_off[256];          // chunk offsets
__device__ int      g_part[256];
__device__ int      g_csr[N_EDGES];
__device__ int      g_gstart[N_GRAPHS + 1];

__device__ __forceinline__ int ptr_at(int i) {
    if (i >= N_NODES) return N_EDGES;
    return g_ptrL[i] + g_off[i >> 8];
}

// ---------------- CSR helpers -------------------------------------------------
__global__ void hist_gstart_kernel(const int* __restrict__ dst, int* __restrict__ deg,
                                   const int* __restrict__ cluster, int* __restrict__ gstart) {
    int i = blockIdx.x * blockDim.x + threadIdx.x;
    if (i < N_EDGES) atomicAdd(&deg[dst[i]], 1);
    if (i <= N_GRAPHS) {
        if (i == N_GRAPHS) gstart[i] = N_NODES;
        else {
            int lo = 0, hi = N_NODES;
            while (lo < hi) {
                int mid = (lo + hi) >> 1;
                if (cluster[mid] < i) lo = mid + 1; else hi = mid;
            }
            gstart[i] = lo;
        }
    }
}

// per-chunk local exclusive scan (256 nodes per block)
__global__ void scan1_kernel(const int* __restrict__ deg, int* __restrict__ ptrL,
                             int* __restrict__ part) {
    __shared__ int s[256];
    int t = threadIdx.x;
    int i = blockIdx.x * 256 + t;
    int d = (i < N_NODES) ? deg[i] : 0;
    s[t] = d;
    __syncthreads();
#pragma unroll
    for (int off = 1; off < 256; off <<= 1) {
        int v = (t >= off) ? s[t - off] : 0;
        __syncthreads();
        s[t] += v;
        __syncthreads();
    }
    if (i < N_NODES) ptrL[i] = s[t] - d;
    if (t == 255) part[blockIdx.x] = s[255];
}

// scan 196 chunk totals -> chunk offsets
__global__ void scan2_kernel(const int* __restrict__ part, int* __restrict__ off) {
    __shared__ int s[256];
    int t = threadIdx.x;
    int v0 = (t < NCHUNK) ? part[t] : 0;
    s[t] = v0;
    __syncthreads();
#pragma unroll
    for (int off2 = 1; off2 < 256; off2 <<= 1) {
        int v = (t >= off2) ? s[t - off2] : 0;
        __syncthreads();
        s[t] += v;
        __syncthreads();
    }
    off[t] = s[t] - v0;  // exclusive
}

__global__ void fill_kernel(const int* __restrict__ src, const int* __restrict__ dst,
                            int* __restrict__ fill, int* __restrict__ csr) {
    int i = blockIdx.x * blockDim.x + threadIdx.x;
    if (i >= N_EDGES) return;
    int d = dst[i];
    int pos = g_ptrL[d] + g_off[d >> 8] + atomicAdd(&fill[d], 1);
    csr[pos] = src[i];
}

// ---------------- bf16 split/pack helpers ------------------------------------
__device__ __forceinline__ uint32_t pack_split(float x, float y, uint32_t& lo) {
    __nv_bfloat16 hx = __float2bfloat16(x);
    __nv_bfloat16 hy = __float2bfloat16(y);
    float rx = x - __bfloat162float(hx);
    float ry = y - __bfloat162float(hy);
    __nv_bfloat16 lx = __float2bfloat16(rx);
    __nv_bfloat16 ly = __float2bfloat16(ry);
    uint16_t bhx = *reinterpret_cast<uint16_t*>(&hx);
    uint16_t bhy = *reinterpret_cast<uint16_t*>(&hy);
    uint16_t blx = *reinterpret_cast<uint16_t*>(&lx);
    uint16_t bly = *reinterpret_cast<uint16_t*>(&ly);
    lo = ((uint32_t)bly << 16) | blx;
    return ((uint32_t)bhy << 16) | bhx;
}

// ---- combined packing: blocks [0,MT_PAD) pack A; rest pack the 6 weights ----
__global__ void pack_all_kernel(const float* __restrict__ A,
                                const float* W0, const float* W1, const float* W2,
                                const float* W3, const float* W4, const float* W5,
                                uint32_t* __restrict__ Ah, uint32_t* __restrict__ Al,
                                uint32_t* __restrict__ Wh, uint32_t* __restrict__ Wl) {
    int warp = threadIdx.x >> 5;
    int lane = threadIdx.x & 31;
    int gidl = lane >> 2, tig = lane & 3;

    if (blockIdx.x < MT_PAD) {
        int it = blockIdx.x * 8 + warp;
        int mt = it >> 3, kt = it & 7;
        uint32_t h[4], l[4];
#pragma unroll
        for (int r = 0; r < 4; r++) {
            int row = mt * 16 + gidl + (r & 1) * 8;
            int col = kt * 16 + tig * 2 + (r >> 1) * 8;
            float2 v = make_float2(0.f, 0.f);
            if (row < N_NODES) v = *reinterpret_cast<const float2*>(&A[row * 128 + col]);
            h[r] = pack_split(v.x, v.y, l[r]);
        }
        *reinterpret_cast<uint4*>(&Ah[(it * 32 + lane) * 4]) = make_uint4(h[0], h[1], h[2], h[3]);
        *reinterpret_cast<uint4*>(&Al[(it * 32 + lane) * 4]) = make_uint4(l[0], l[1], l[2], l[3]);
        return;
    }

    int wit = (blockIdx.x - MT_PAD) * 8 + warp;   // 0..639
    if (wit >= 640) return;
    const float* W;
    int BNs, dst_mat, nt_off, tile;
    if (wit < 512) {
        int m = wit >> 7;
        tile = wit & 127;
        BNs = 128; dst_mat = m; nt_off = 0;
        W = (m == 0) ? W0 : (m == 1) ? W1 : (m == 2) ? W2 : W3;
    } else {
        int m = (wit - 512) >> 6;
        tile = (wit - 512) & 63;
        BNs = 64; dst_mat = 4; nt_off = m ? 8 : 0;
        W = m ? W5 : W4;
    }
    int NTs = BNs / 8;
    int kt = tile / NTs, nt = tile % NTs;
    int col = nt * 8 + gidl;
    uint32_t h[2], l[2];
#pragma unroll
    for (int r = 0; r < 2; r++) {
        int k = kt * 16 + tig * 2 + r * 8;
        float v0 = W[k * BNs + col];
        float v1 = W[(k + 1) * BNs + col];
        h[r] = pack_split(v0, v1, l[r]);
    }
    int didx = dst_mat * 8192 + (kt * 16 + nt + nt_off) * 64 + lane * 2;
    *reinterpret_cast<uint2*>(&Wh[didx]) = make_uint2(h[0], h[1]);
    *reinterpret_cast<uint2*>(&Wl[didx]) = make_uint2(l[0], l[1]);
}

// ---------------- bf16 split GEMM --------------------------------------------
__device__ __forceinline__ uint32_t smem_u32(const void* p) {
    uint32_t a;
    asm("{ .reg .u64 t; cvta.to.shared.u64 t, %1; cvt.u32.u64 %0, t; }" : "=r"(a) : "l"(p));
    return a;
}

__device__ __forceinline__ void cp16(uint32_t dst, const void* src) {
    asm volatile("cp.async.cg.shared.global [%0], [%1], 16;" :: "r"(dst), "l"(src) : "memory");
}

#define MMA_BF16(c, a, b)                                                         \
    asm volatile(                                                                 \
        "mma.sync.aligned.m16n8k16.row.col.f32.bf16.bf16.f32 "                    \
        "{%0,%1,%2,%3},{%4,%5,%6,%7},{%8,%9},{%0,%1,%2,%3};"                      \
        : "+f"(c[0]), "+f"(c[1]), "+f"(c[2]), "+f"(c[3])                          \
        : "r"(a[0]), "r"(a[1]), "r"(a[2]), "r"(a[3]), "r"(b[0]), "r"(b[1]))

__global__ __launch_bounds__(256, 2) void bf16_gemm(
    const uint32_t* __restrict__ Ah, const uint32_t* __restrict__ Al,
    const uint32_t* __restrict__ Bh0, const uint32_t* __restrict__ Bl0,
    const uint32_t* __restrict__ Bh1, const uint32_t* __restrict__ Bl1,
    __half* __restrict__ C0h, float* __restrict__ C1, int M) {
    constexpr int NT = 16;
    constexpr int STAGE = 16384 + 16384;
    extern __shared__ char smem[];

    const uint32_t* Bh = blockIdx.y ? Bh1 : Bh0;
    const uint32_t* Bl = blockIdx.y ? Bl1 : Bl0;

    uint32_t sb = smem_u32(smem);
    int tid = threadIdx.x, lane = tid & 31, warp = tid >> 5;
    int wm = warp & 1, wn = warp >> 1;
    int bRow = blockIdx.x * 128;

    float acc[4][4][4];
#pragma unroll
    for (int mt = 0; mt < 4; mt++)
#pragma unroll
        for (int nt = 0; nt < 4; nt++)
#pragma unroll
            for (int j = 0; j < 4; j++) acc[mt][nt][j] = 0.f;

    auto load_stage = [&](int kc, int buf) {
#pragma unroll
        for (int i = 0; i < 4; i++) {
            int c = tid + i * 256;
            int t = c >> 5, o = (c & 31) * 16;
            int pl = t >> 4, kt = (t >> 3) & 1, mt = t & 7;
            const uint32_t* src = (pl ? Al : Ah) +
                ((blockIdx.x * 8 + mt) * 8 + kc * 2 + kt) * 128;
            cp16(sb + buf * STAGE + t * 512 + o, (const char*)src + o);
        }
#pragma unroll
        for (int i = 0; i < 4; i++) {
            int c = tid + i * 256;
            int t = c >> 4, o = (c & 15) * 16;
            int pl = t / 32;
            int kt = (t / 16) & 1;
            int nt = t % 16;
            const uint32_t* src = (pl ? Bl : Bh) + ((kc * 2 + kt) * NT + nt) * 64;
            cp16(sb + buf * STAGE + 16384 + t * 256 + o, (const char*)src + o);
        }
        asm volatile("cp.async.commit_group;" ::: "memory");
    };

    auto compute = [&](int buf) {
#pragma unroll
        for (int kt = 0; kt < 2; kt++) {
            uint32_t a[2][4][4];
#pragma unroll
            for (int pl = 0; pl < 2; pl++)
#pragma unroll
                for (int mt = 0; mt < 4; mt++) {
                    uint32_t ad = sb + buf * STAGE +
                        (((pl * 2 + kt) * 8) + (wm * 4 + mt)) * 512 + lane * 16;
                    asm volatile("ld.shared.v4.b32 {%0,%1,%2,%3},[%4];"
                        : "=r"(a[pl][mt][0]), "=r"(a[pl][mt][1]),
                          "=r"(a[pl][mt][2]), "=r"(a[pl][mt][3]) : "r"(ad));
                }
            uint32_t b[2][4][2];
#pragma unroll
            for (int pl = 0; pl < 2; pl++)
#pragma unroll
                for (int nt = 0; nt < 4; nt++) {
                    uint32_t ad = sb + buf * STAGE + 16384 +
                        ((pl * 2 + kt) * NT + wn * 4 + nt) * 256 + lane * 8;
                    asm volatile("ld.shared.v2.b32 {%0,%1},[%2];"
                        : "=r"(b[pl][nt][0]), "=r"(b[pl][nt][1]) : "r"(ad));
                }
#pragma unroll
            for (int mt = 0; mt < 4; mt++)
#pragma unroll
                for (int nt = 0; nt < 4; nt++) {
                    MMA_BF16(acc[mt][nt], a[0][mt], b[0][nt]);
                    MMA_BF16(acc[mt][nt], a[0][mt], b[1][nt]);
                    MMA_BF16(acc[mt][nt], a[1][mt], b[0][nt]);
                }
        }
    };

    load_stage(0, 0);
    for (int kc = 0; kc < 4; kc++) {
        if (kc < 3) {
            load_stage(kc + 1, (kc + 1) & 1);
            asm volatile("cp.async.wait_group 1;" ::: "memory");
        } else {
            asm volatile("cp.async.wait_group 0;" ::: "memory");
        }
        __syncthreads();
        compute(kc & 1);
        __syncthreads();
    }

    int gid = lane >> 2, tig = lane & 3;
#pragma unroll
    for (int mt = 0; mt < 4; mt++) {
        int row = bRow + wm * 64 + mt * 16 + gid;
#pragma unroll
        for (int nt = 0; nt < 4; nt++) {
            int col = wn * 32 + nt * 8 + tig * 2;
            if (blockIdx.y == 0) {
                if (row < M)
                    *reinterpret_cast<__half2*>(&C0h[row * 128 + col]) =
                        __floats2half2_rn(acc[mt][nt][0], acc[mt][nt][1]);
                if (row + 8 < M)
                    *reinterpret_cast<__half2*>(&C0h[(row + 8) * 128 + col]) =
                        __floats2half2_rn(acc[mt][nt][2], acc[mt][nt][3]);
            } else {
                if (row < M)
                    *reinterpret_cast<float2*>(&C1[row * 128 + col]) =
                        make_float2(acc[mt][nt][0], acc[mt][nt][1]);
                if (row + 8 < M)
                    *reinterpret_cast<float2*>(&C1[(row + 8) * 128 + col]) =
                        make_float2(acc[mt][nt][2], acc[mt][nt][3]);
            }
        }
    }
}

// ------- aggregation (fp16 gather) + fused fragment-packing ------------------
__global__ void agg128_pack_kernel(const __half* __restrict__ yh, const float* __restrict__ z,
                                   const float* __restrict__ bl,
                                   const int* __restrict__ csr,
                                   uint32_t* __restrict__ Ah, uint32_t* __restrict__ Al,
                                   float* __restrict__ out_pre,
                                   float* __restrict__ out_f32) {
    int node = blockIdx.x * 8 + (threadIdx.x >> 5);
    if (node >= N_NODES) return;
    int lane = threadIdx.x & 31;

    int lo = ptr_at(node), hi = ptr_at(node + 1);
    float4 acc = make_float4(0.f, 0.f, 0.f, 0.f);
#pragma unroll 8
    for (int e = lo; e < hi; e++) {
        int s = csr[e];
        uint2 raw = *reinterpret_cast<const uint2*>(&yh[s * 128 + lane * 4]);
        __half2 p0 = *reinterpret_cast<__half2*>(&raw.x);
        __half2 p1 = *reinterpret_cast<__half2*>(&raw.y);
        float2 f0 = __half22float2(p0);
        float2 f1 = __half22float2(p1);
        acc.x += f0.x; acc.y += f0.y; acc.z += f1.x; acc.w += f1.y;
    }
    float inv = 1.f / (float)max(hi - lo, 1);
    float4 b = *reinterpret_cast<const float4*>(&bl[lane * 4]);
    float4 zi = *reinterpret_cast<const float4*>(&z[node * 128 + lane * 4]);
    float4 h;
    h.x = acc.x * inv + b.x + zi.x;
    h.y = acc.y * inv + b.y + zi.y;
    h.z = acc.z * inv + b.z + zi.z;
    h.w = acc.w * inv + b.w + zi.w;
    if (out_pre) *reinterpret_cast<float4*>(&out_pre[node * 128 + lane * 4]) = h;
    float4 r = make_float4(fmaxf(h.x, 0.f), fmaxf(h.y, 0.f), fmaxf(h.z, 0.f), fmaxf(h.w, 0.f));
    if (out_f32) *reinterpret_cast<float4*>(&out_f32[node * 128 + lane * 4]) = r;

    int mt = node >> 4, gid = node & 7, rowhalf = (node >> 3) & 1;
    int kt = lane >> 2;
    float v01[2] = {r.x, r.z};
    float v11[2] = {r.y, r.w};
#pragma unroll
    for (int p = 0; p < 2; p++) {
        int c = lane * 4 + 2 * p;
        int ct = c & 15;
        int tig = (ct & 7) >> 1;
        int colhalf = ct >> 3;
        int reg = rowhalf + 2 * colhalf;
        int idx = ((mt * 8 + kt) * 32 + gid * 4 + tig) * 4 + reg;
        uint32_t lo32;
        uint32_t hi32 = pack_split(v01[p], v11[p], lo32);
        Ah[idx] = hi32;
        Al[idx] = lo32;
    }
}

// ------- final: lsm (blocks<AGG_BLOCKS) + pool (next 64) + scratch re-zero ---
__global__ void final_kernel(const __half* __restrict__ yzh,
                             const float* __restrict__ bl,
                             const int* __restrict__ csr,
                             const float* __restrict__ x2,
                             const int* __restrict__ gstart,
                             float* __restrict__ out_lsm,
                             float* __restrict__ out_g) {
    int lane = threadIdx.x & 31;
    int warp = threadIdx.x >> 5;

    // re-zero scratch counters for next run (deterministic: starts zeroed)
    {
        int gtid = blockIdx.x * blockDim.x + threadIdx.x;
        if (gtid < N_NODES) { g_deg[gtid] = 0; g_fill[gtid] = 0; }
    }

    if (blockIdx.x < AGG_BLOCKS) {
        int node = blockIdx.x * 8 + warp;
        if (node >= N_NODES) return;
        int lo = ptr_at(node), hi = ptr_at(node + 1);
        float2 acc = make_float2(0.f, 0.f);
#pragma unroll 8
        for (int e = lo; e < hi; e++) {
            int s = csr[e];
            __half2 v = *reinterpret_cast<const __half2*>(&yzh[s * 128 + lane * 2]);
            float2 f = __half22float2(v);
            acc.x += f.x; acc.y += f.y;
        }
        float inv = 1.f / (float)max(hi - lo, 1);
        float2 b = *reinterpret_cast<const float2*>(&bl[lane * 2]);
        __half2 zv = *reinterpret_cast<const __half2*>(&yzh[node * 128 + 64 + lane * 2]);
        float2 zi = __half22float2(zv);
        float2 h;
        h.x = acc.x * inv + b.x + zi.x;
        h.y = acc.y * inv + b.y + zi.y;

        float m = fmaxf(h.x, h.y);
#pragma unroll
        for (int off = 16; off > 0; off >>= 1)
            m = fmaxf(m, __shfl_xor_sync(0xFFFFFFFFu, m, off));
        float s = expf(h.x - m) + expf(h.y - m);
#pragma unroll
        for (int off = 16; off > 0; off >>= 1)
            s += __shfl_xor_sync(0xFFFFFFFFu, s, off);
        float ls = logf(s);
        *reinterpret_cast<float2*>(&out_lsm[node * 64 + lane * 2]) =
            make_float2(h.x - m - ls, h.y - m - ls);
    } else {
        int g = (blockIdx.x - AGG_BLOCKS) * 8 + warp;
        if (g >= N_GRAPHS) return;
        int lo = gstart[g], hi = gstart[g + 1];
        float4 acc = make_float4(0.f, 0.f, 0.f, 0.f);
        for (int i = lo; i < hi; i++) {
            float4 v = *reinterpret_cast<const float4*>(&x2[i * 128 + lane * 4]);
            acc.x += v.x; acc.y += v.y; acc.z += v.z; acc.w += v.w;
        }
        float inv = 1.f / (float)max(hi - lo, 1);
        acc.x *= inv; acc.y *= inv; acc.z *= inv; acc.w *= inv;
        *reinterpret_cast<float4*>(&out_g[g * 128 + lane * 4]) = acc;
    }
}

// ---------------- launch -----------------------------------------------------
extern "C" void kernel_launch(void* const* d_in, const int* in_sizes, int n_in,
                              void* d_out, int out_size) {
    const float* x       = (const float*)d_in[0];
    const int*   ei      = (const int*)d_in[1];
    const int*   cluster = (const int*)d_in[2];
    const float* Wl0 = (const float*)d_in[3];
    const float* bl0 = (const float*)d_in[4];
    const float* Wr0 = (const float*)d_in[5];
    const float* Wl1 = (const float*)d_in[6];
    const float* bl1 = (const float*)d_in[7];
    const float* Wr1 = (const float*)d_in[8];
    const float* Wl2 = (const float*)d_in[9];
    const float* bl2 = (const float*)d_in[10];
    const float* Wr2 = (const float*)d_in[11];

    const int* src = ei;
    const int* dst = ei + N_EDGES;

    float* out = (float*)d_out;
    float* out_lsm = out;
    float* out_pre = out + N_NODES * C_OUT;
    float* out_g   = out + N_NODES * C_OUT + N_NODES * C_HID;

    __half* yh;
    float *z, *x2;
    uint32_t *ah, *al, *wh, *wl;
    int *deg, *fill, *csr, *gstart;
    cudaGetSymbolAddress((void**)&yh, g_yh);
    cudaGetSymbolAddress((void**)&z, g_z);
    cudaGetSymbolAddress((void**)&x2, g_x2);
    cudaGetSymbolAddress((void**)&ah, g_ah);
    cudaGetSymbolAddress((void**)&al, g_al);
    cudaGetSymbolAddress((void**)&wh, g_wh);
    cudaGetSymbolAddress((void**)&wl, g_wl);
    cudaGetSymbolAddress((void**)&deg, g_deg);
    cudaGetSymbolAddress((void**)&fill, g_fill);
    cudaGetSymbolAddress((void**)&csr, g_csr);
    cudaGetSymbolAddress((void**)&gstart, g_gstart);

    int *ptrL, *offp, *part;
    cudaGetSymbolAddress((void**)&ptrL, g_ptrL);
    cudaGetSymbolAddress((void**)&offp, g_off);
    cudaGetSymbolAddress((void**)&part, g_part);

    const int SMEM128 = 2 * (16384 + 16384);  // 65536
    cudaFuncSetAttribute(bf16_gemm, cudaFuncAttributeMaxDynamicSharedMemorySize, SMEM128);

    // ---- fork: CSR build on side stream (deg/fill pre-zeroed by prior run) ----
    cudaStream_t sb;
    cudaStreamCreateWithFlags(&sb, cudaStreamNonBlocking);
    cudaEvent_t eFork, eJoin;
    cudaEventCreateWithFlags(&eFork, cudaEventDisableTiming);
    cudaEventCreateWithFlags(&eJoin, cudaEventDisableTiming);

    cudaEventRecord(eFork, 0);
    cudaStreamWaitEvent(sb, eFork, 0);
    const int EDGE_GRID = (N_EDGES + 255) / 256;
    hist_gstart_kernel<<<EDGE_GRID, 256, 0, sb>>>(dst, deg, cluster, gstart);
    scan1_kernel<<<NCHUNK, 256, 0, sb>>>(deg, ptrL, part);
    scan2_kernel<<<1, 256, 0, sb>>>(part, offp);
    fill_kernel<<<EDGE_GRID, 256, 0, sb>>>(src, dst, fill, csr);
    cudaEventRecord(eJoin, sb);

    // main stream: combined pack + layer0 GEMM
    pack_all_kernel<<<MT_PAD + 80, 256>>>(x, Wl0, Wr0, Wl1, Wr1, Wl2, Wr2,
                                          ah, al, wh, wl);

    dim3 gg(391, 2);
    bf16_gemm<<<gg, 256, SMEM128>>>(ah, al,
        wh + 0 * 8192, wl + 0 * 8192, wh + 1 * 8192, wl + 1 * 8192, yh, z, N_NODES);

    cudaStreamWaitEvent(0, eJoin, 0);

    // ---- layer 0 aggregation ----
    agg128_pack_kernel<<<AGG_BLOCKS, 256>>>(yh, z, bl0, csr, ah, al, nullptr, nullptr);

    // ---- layer 1 ----
    bf16_gemm<<<gg, 256, SMEM128>>>(ah, al,
        wh + 2 * 8192, wl + 2 * 8192, wh + 3 * 8192, wl + 3 * 8192, yh, z, N_NODES);
    agg128_pack_kernel<<<AGG_BLOCKS, 256>>>(yh, z, bl1, csr, ah, al, out_pre, x2);

    // ---- layer 2 fused GEMM ([Wl2|Wr2]) ----
    dim3 gg1(391, 1);
    bf16_gemm<<<gg1, 256, SMEM128>>>(ah, al,
        wh + 4 * 8192, wl + 4 * 8192, wh + 4 * 8192, wl + 4 * 8192, yh, nullptr, N_NODES);

    // ---- final: log-softmax agg + pooling + scratch re-zero ----
    final_kernel<<<AGG_BLOCKS + 64, 256>>>(yh, bl2, csr, x2, gstart, out_lsm, out_g);
}